// round 9
// baseline (speedup 1.0000x reference)
#include <cuda_runtime.h>
#include <cuda_bf16.h>
#include <cstdint>

// Fixed shapes: N=16384 rows, C=2048 classes, D=512
#define N_ROWS 16384
#define N_CLS  2048
#define DIM    512
#define MARGIN 1.0f

// ---------------- device scratch (no runtime allocation) ----------------
__device__ __nv_bfloat16 g_WO_bf[N_ROWS * DIM];  // normalized WO, bf16
__device__ __nv_bfloat16 g_E_bf [N_CLS * DIM];   // emb, bf16
__device__ float    d_x2[N_ROWS];                // ||normalized row||^2 (fp32)
__device__ float    d_e2[N_CLS];                 // ||emb_c||^2 (fp32)
__device__ float    d_labelD2[N_ROWS];           // d^2 to true class
__device__ unsigned d_minBits[N_ROWS];           // min d^2 over other classes (float bits)
__device__ float    d_partial[64];               // partial loss sums

// ---------------- helpers ----------------
__device__ __forceinline__ uint32_t smem_to_u32(const void* p) {
    uint32_t a;
    asm("{ .reg .u64 t; cvta.to.shared.u64 t, %1; cvt.u32.u64 %0, t; }" : "=r"(a) : "l"(p));
    return a;
}
#define CP_ASYNC_16(dst_u32, src_ptr) \
    asm volatile("cp.async.cg.shared.global [%0], [%1], 16;" :: "r"(dst_u32), "l"(src_ptr))
#define CP_ASYNC_COMMIT() asm volatile("cp.async.commit_group;" ::: "memory")
#define CP_ASYNC_WAIT1()  asm volatile("cp.async.wait_group 1;" ::: "memory")
#define CP_ASYNC_WAIT0()  asm volatile("cp.async.wait_group 0;" ::: "memory")
#define SW128(off) ((off) ^ (((off) >> 3) & 0x70))

__device__ __forceinline__ void ldsm_x4(uint32_t* r, uint32_t addr) {
    asm volatile("ldmatrix.sync.aligned.m8n8.x4.shared.b16 {%0,%1,%2,%3}, [%4];"
        : "=r"(r[0]), "=r"(r[1]), "=r"(r[2]), "=r"(r[3]) : "r"(addr));
}
__device__ __forceinline__ void mma_16816(float* c, const uint32_t* a, const uint32_t* b) {
    asm volatile(
        "mma.sync.aligned.m16n8k16.row.col.f32.bf16.bf16.f32 "
        "{%0,%1,%2,%3}, {%4,%5,%6,%7}, {%8,%9}, {%0,%1,%2,%3};"
        : "+f"(c[0]), "+f"(c[1]), "+f"(c[2]), "+f"(c[3])
        : "r"(a[0]), "r"(a[1]), "r"(a[2]), "r"(a[3]), "r"(b[0]), "r"(b[1]));
}

// ---------------- kernel 1: normalize WO -> bf16, x2, init minBits ----------------
__global__ void prep_wo(const float* __restrict__ WO) {
    int row = blockIdx.x * 8 + (threadIdx.x >> 5);
    int lane = threadIdx.x & 31;
    const float4* src = reinterpret_cast<const float4*>(WO + (size_t)row * DIM);
    float4 v[4];
    float s = 0.f;
    #pragma unroll
    for (int c = 0; c < 4; ++c) {
        v[c] = src[lane + 32 * c];
        s += v[c].x * v[c].x + v[c].y * v[c].y + v[c].z * v[c].z + v[c].w * v[c].w;
    }
    #pragma unroll
    for (int off = 16; off > 0; off >>= 1) s += __shfl_xor_sync(0xffffffffu, s, off);
    float inv = 1.f / fmaxf(sqrtf(s), 1e-12f);
    if (lane == 0) {
        d_x2[row] = (s * inv) * inv;
        d_minBits[row] = 0x7F800000u;  // +inf
    }
    uint2* dst = reinterpret_cast<uint2*>(g_WO_bf + (size_t)row * DIM);
    #pragma unroll
    for (int c = 0; c < 4; ++c) {
        __nv_bfloat162 p0 = __float22bfloat162_rn(make_float2(v[c].x * inv, v[c].y * inv));
        __nv_bfloat162 p1 = __float22bfloat162_rn(make_float2(v[c].z * inv, v[c].w * inv));
        uint2 u;
        u.x = *reinterpret_cast<uint32_t*>(&p0);
        u.y = *reinterpret_cast<uint32_t*>(&p1);
        dst[lane + 32 * c] = u;
    }
}

// ---------------- kernel 2: emb -> bf16, e2 ----------------
__global__ void prep_e(const float* __restrict__ E) {
    int row = blockIdx.x * 8 + (threadIdx.x >> 5);
    int lane = threadIdx.x & 31;
    const float4* src = reinterpret_cast<const float4*>(E + (size_t)row * DIM);
    float4 v[4];
    float s = 0.f;
    #pragma unroll
    for (int c = 0; c < 4; ++c) {
        v[c] = src[lane + 32 * c];
        s += v[c].x * v[c].x + v[c].y * v[c].y + v[c].z * v[c].z + v[c].w * v[c].w;
    }
    #pragma unroll
    for (int off = 16; off > 0; off >>= 1) s += __shfl_xor_sync(0xffffffffu, s, off);
    if (lane == 0) d_e2[row] = s;
    uint2* dst = reinterpret_cast<uint2*>(g_E_bf + (size_t)row * DIM);
    #pragma unroll
    for (int c = 0; c < 4; ++c) {
        __nv_bfloat162 p0 = __float22bfloat162_rn(make_float2(v[c].x, v[c].y));
        __nv_bfloat162 p1 = __float22bfloat162_rn(make_float2(v[c].z, v[c].w));
        uint2 u;
        u.x = *reinterpret_cast<uint32_t*>(&p0);
        u.y = *reinterpret_cast<uint32_t*>(&p1);
        dst[lane + 32 * c] = u;
    }
}

// ---------------- fused mma.sync GEMM + d2/min/label epilogue ----------------
// Grid (16, 64): x = 128-col tile, y = 256-row tile. 512 threads = 16 warps (4 M x 4 N).
// CTA tile 256x128, BK=64, 3-stage cp.async pipeline (one __syncthreads per k-iter),
// SW128 swizzle. Warp tile 64x32 = 4x4 m16n8k16, fp32 accumulate (64 acc regs).
#define STAGE_BYTES 49152         // A 32768 + B 16384
#define SMEM_B_IN_STAGE 32768
#define SMEM_RM_OFF (3 * STAGE_BYTES)          // 147456, 256 x 4B
#define SMEM_GEMM_TOTAL (SMEM_RM_OFF + 1024)   // 148480

__global__ __launch_bounds__(512, 1)
void gemm_mma(const int* __restrict__ label) {
    extern __shared__ char smem[];
    const uint32_t smem_u32 = smem_to_u32(smem);
    const int tid  = threadIdx.x;
    const int lane = tid & 31;
    const int wid  = tid >> 5;
    const int warpM = wid >> 2;          // 0..3 -> rows warpM*64
    const int warpN = wid & 3;           // 0..3 -> cols warpN*32
    const int rowBase = blockIdx.y * 256;
    const int colBase = blockIdx.x * 128;

    unsigned* rowMinS = reinterpret_cast<unsigned*>(smem + SMEM_RM_OFF);
    if (tid < 256) rowMinS[tid] = 0x7F800000u;

    // stage loader: A 256x64 bf16 (2048 16B chunks) + B 128x64 (1024 chunks), 6/thread
    auto loadTile = [&](int kt, int s) {
        uint32_t sbase = smem_u32 + s * STAGE_BYTES;
        #pragma unroll
        for (int i = 0; i < 4; ++i) {
            int q = tid + 512 * i;           // 0..2047
            int row = q >> 3, kc = q & 7;
            const void* srcA = g_WO_bf + (size_t)(rowBase + row) * DIM + kt * 64 + kc * 8;
            CP_ASYNC_16(sbase + SW128(row * 128 + kc * 16), srcA);
        }
        #pragma unroll
        for (int i = 0; i < 2; ++i) {
            int q = tid + 512 * i;           // 0..1023
            int row = q >> 3, kc = q & 7;
            const void* srcB = g_E_bf + (size_t)(colBase + row) * DIM + kt * 64 + kc * 8;
            CP_ASYNC_16(sbase + SMEM_B_IN_STAGE + SW128(row * 128 + kc * 16), srcB);
        }
        CP_ASYNC_COMMIT();
    };

    float acc[4][4][4];
    #pragma unroll
    for (int mt = 0; mt < 4; ++mt)
        #pragma unroll
        for (int nt = 0; nt < 4; ++nt)
            #pragma unroll
            for (int e = 0; e < 4; ++e) acc[mt][nt][e] = 0.f;

    const int aRowOff = (warpM * 64 + (lane & 7) + ((lane >> 3) & 1) * 8) * 128 + (lane >> 4) * 16;
    const int bRowOff = (warpN * 32 + (lane & 7) + (lane >> 4) * 8) * 128 + ((lane >> 3) & 1) * 16;

    loadTile(0, 0);
    loadTile(1, 1);

    #pragma unroll 1
    for (int kt = 0; kt < 8; ++kt) {
        if (kt < 6) CP_ASYNC_WAIT1();
        else        CP_ASYNC_WAIT0();
        __syncthreads();                     // stage kt resident for all; stage kt-1 reads done
        if (kt + 2 < 8) loadTile(kt + 2, (kt + 2) % 3);   // overwrites slot of stage kt-1

        const uint32_t sA = smem_u32 + (kt % 3) * STAGE_BYTES;
        const uint32_t sB = sA + SMEM_B_IN_STAGE;
        #pragma unroll
        for (int ks = 0; ks < 4; ++ks) {
            uint32_t aF[4][4], bF[4][2];
            #pragma unroll
            for (int mt = 0; mt < 4; ++mt)
                ldsm_x4(aF[mt], sA + SW128(aRowOff + mt * 2048 + ks * 32));
            #pragma unroll
            for (int pr = 0; pr < 2; ++pr) {
                uint32_t t[4];
                ldsm_x4(t, sB + SW128(bRowOff + pr * 2048 + ks * 32));
                bF[2 * pr + 0][0] = t[0]; bF[2 * pr + 0][1] = t[1];
                bF[2 * pr + 1][0] = t[2]; bF[2 * pr + 1][1] = t[3];
            }
            #pragma unroll
            for (int mt = 0; mt < 4; ++mt)
                #pragma unroll
                for (int nt = 0; nt < 4; ++nt)
                    mma_16816(acc[mt][nt], aF[mt], bF[nt]);
        }
    }
    __syncthreads();

    // epilogue in d^2 space: d2 = x2 + e2 - 2*dot; exclude label col from min
    #pragma unroll
    for (int mt = 0; mt < 4; ++mt) {
        #pragma unroll
        for (int half = 0; half < 2; ++half) {
            int rl = warpM * 64 + mt * 16 + (lane >> 2) + half * 8;
            int r  = rowBase + rl;
            float x2v = __ldg(&d_x2[r]);
            int   lab = __ldg(&label[r]);
            float m = __int_as_float(0x7f800000);
            #pragma unroll
            for (int nt = 0; nt < 4; ++nt) {
                int c0 = colBase + warpN * 32 + nt * 8 + 2 * (lane & 3);
                float d20 = fmaf(-2.f, acc[mt][nt][half * 2 + 0], x2v + __ldg(&d_e2[c0]));
                float d21 = fmaf(-2.f, acc[mt][nt][half * 2 + 1], x2v + __ldg(&d_e2[c0 + 1]));
                if (c0 == lab)     d_labelD2[r] = d20;
                else               m = fminf(m, d20);
                if (c0 + 1 == lab) d_labelD2[r] = d21;
                else               m = fminf(m, d21);
            }
            m = fminf(m, __shfl_xor_sync(0xffffffffu, m, 1));
            m = fminf(m, __shfl_xor_sync(0xffffffffu, m, 2));
            if ((lane & 3) == 0) atomicMin(&rowMinS[rl], __float_as_uint(m));
        }
    }
    __syncthreads();
    if (tid < 256)
        atomicMin(&d_minBits[rowBase + tid], rowMinS[tid]);
}

// ---------------- loss reduction (2-stage) ----------------
__global__ void partial_loss() {
    int tid = threadIdx.x;
    int n = blockIdx.x * 256 + tid;
    float ld = sqrtf(fmaxf(d_labelD2[n], 0.f));
    float md = sqrtf(fmaxf(__uint_as_float(d_minBits[n]), 0.f));
    float s = MARGIN + ld - md;
    #pragma unroll
    for (int off = 16; off > 0; off >>= 1) s += __shfl_xor_sync(0xffffffffu, s, off);
    __shared__ float sb[8];
    if ((tid & 31) == 0) sb[tid >> 5] = s;
    __syncthreads();
    if (tid < 8) {
        float v = sb[tid];
        v += __shfl_xor_sync(0xffu, v, 1);
        v += __shfl_xor_sync(0xffu, v, 2);
        v += __shfl_xor_sync(0xffu, v, 4);
        if (tid == 0) d_partial[blockIdx.x] = v;
    }
}
__global__ void final_loss(float* __restrict__ out) {
    int tid = threadIdx.x;   // 64
    float v = d_partial[tid];
    #pragma unroll
    for (int off = 16; off > 0; off >>= 1) v += __shfl_xor_sync(0xffffffffu, v, off);
    __shared__ float sb[2];
    if ((tid & 31) == 0) sb[tid >> 5] = v;
    __syncthreads();
    if (tid == 0) out[0] = (sb[0] + sb[1]) / (float)N_ROWS;
}

// ---------------- launch ----------------
extern "C" void kernel_launch(void* const* d_in, const int* in_sizes, int n_in,
                              void* d_out, int out_size) {
    const float* WO    = (const float*)d_in[0];
    const float* E     = (const float*)d_in[1];
    const int*   label = (const int*)d_in[2];
    float* out = (float*)d_out;

    cudaFuncSetAttribute(gemm_mma, cudaFuncAttributeMaxDynamicSharedMemorySize, SMEM_GEMM_TOTAL);

    prep_wo<<<N_ROWS / 8, 256>>>(WO);
    prep_e<<<N_CLS / 8, 256>>>(E);
    dim3 grid(N_CLS / 128, N_ROWS / 256);   // (16, 64)
    gemm_mma<<<grid, 512, SMEM_GEMM_TOTAL>>>(label);
    partial_loss<<<64, 256>>>();
    final_loss<<<1, 64>>>(out);
}

// round 10
// speedup vs baseline: 1.1018x; 1.1018x over previous
#include <cuda_runtime.h>
#include <cuda_bf16.h>
#include <cstdint>

// Fixed shapes: N=16384 rows, C=2048 classes, D=512
#define N_ROWS 16384
#define N_CLS  2048
#define DIM    512
#define MARGIN 1.0f

// ---------------- device scratch (no runtime allocation) ----------------
__device__ __nv_bfloat16 g_WO_bf[N_ROWS * DIM];  // normalized WO, bf16
__device__ __nv_bfloat16 g_E_bf [N_CLS * DIM];   // emb, bf16
__device__ float    d_x2[N_ROWS];                // ||normalized row||^2 (fp32)
__device__ float    d_e2[N_CLS];                 // ||emb_c||^2 (fp32)
__device__ float    d_labelD2[N_ROWS];           // d^2 to true class
__device__ unsigned d_minBits[N_ROWS];           // min d^2 over other classes (float bits)
__device__ float    d_partial[64];               // partial loss sums

// ---------------- helpers ----------------
__device__ __forceinline__ uint32_t smem_to_u32(const void* p) {
    uint32_t a;
    asm("{ .reg .u64 t; cvta.to.shared.u64 t, %1; cvt.u32.u64 %0, t; }" : "=r"(a) : "l"(p));
    return a;
}
#define CP_ASYNC_16(dst_u32, src_ptr) \
    asm volatile("cp.async.cg.shared.global [%0], [%1], 16;" :: "r"(dst_u32), "l"(src_ptr))
#define CP_ASYNC_COMMIT() asm volatile("cp.async.commit_group;" ::: "memory")
#define CP_ASYNC_WAIT1()  asm volatile("cp.async.wait_group 1;" ::: "memory")
#define CP_ASYNC_WAIT0()  asm volatile("cp.async.wait_group 0;" ::: "memory")
#define SW128(off) ((off) ^ (((off) >> 3) & 0x70))

__device__ __forceinline__ void ldsm_x4(uint32_t* r, uint32_t addr) {
    asm volatile("ldmatrix.sync.aligned.m8n8.x4.shared.b16 {%0,%1,%2,%3}, [%4];"
        : "=r"(r[0]), "=r"(r[1]), "=r"(r[2]), "=r"(r[3]) : "r"(addr));
}
__device__ __forceinline__ void mma_16816(float* c, const uint32_t* a, const uint32_t* b) {
    asm volatile(
        "mma.sync.aligned.m16n8k16.row.col.f32.bf16.bf16.f32 "
        "{%0,%1,%2,%3}, {%4,%5,%6,%7}, {%8,%9}, {%0,%1,%2,%3};"
        : "+f"(c[0]), "+f"(c[1]), "+f"(c[2]), "+f"(c[3])
        : "r"(a[0]), "r"(a[1]), "r"(a[2]), "r"(a[3]), "r"(b[0]), "r"(b[1]));
}

// ---------------- kernel 1: normalize WO -> bf16, x2, init minBits ----------------
__global__ void prep_wo(const float* __restrict__ WO) {
    int row = blockIdx.x * 8 + (threadIdx.x >> 5);
    int lane = threadIdx.x & 31;
    const float4* src = reinterpret_cast<const float4*>(WO + (size_t)row * DIM);
    float4 v[4];
    float s = 0.f;
    #pragma unroll
    for (int c = 0; c < 4; ++c) {
        v[c] = src[lane + 32 * c];
        s += v[c].x * v[c].x + v[c].y * v[c].y + v[c].z * v[c].z + v[c].w * v[c].w;
    }
    #pragma unroll
    for (int off = 16; off > 0; off >>= 1) s += __shfl_xor_sync(0xffffffffu, s, off);
    float inv = 1.f / fmaxf(sqrtf(s), 1e-12f);
    if (lane == 0) {
        d_x2[row] = (s * inv) * inv;
        d_minBits[row] = 0x7F800000u;  // +inf
    }
    uint2* dst = reinterpret_cast<uint2*>(g_WO_bf + (size_t)row * DIM);
    #pragma unroll
    for (int c = 0; c < 4; ++c) {
        __nv_bfloat162 p0 = __float22bfloat162_rn(make_float2(v[c].x * inv, v[c].y * inv));
        __nv_bfloat162 p1 = __float22bfloat162_rn(make_float2(v[c].z * inv, v[c].w * inv));
        uint2 u;
        u.x = *reinterpret_cast<uint32_t*>(&p0);
        u.y = *reinterpret_cast<uint32_t*>(&p1);
        dst[lane + 32 * c] = u;
    }
}

// ---------------- kernel 2: emb -> bf16, e2 ----------------
__global__ void prep_e(const float* __restrict__ E) {
    int row = blockIdx.x * 8 + (threadIdx.x >> 5);
    int lane = threadIdx.x & 31;
    const float4* src = reinterpret_cast<const float4*>(E + (size_t)row * DIM);
    float4 v[4];
    float s = 0.f;
    #pragma unroll
    for (int c = 0; c < 4; ++c) {
        v[c] = src[lane + 32 * c];
        s += v[c].x * v[c].x + v[c].y * v[c].y + v[c].z * v[c].z + v[c].w * v[c].w;
    }
    #pragma unroll
    for (int off = 16; off > 0; off >>= 1) s += __shfl_xor_sync(0xffffffffu, s, off);
    if (lane == 0) d_e2[row] = s;
    uint2* dst = reinterpret_cast<uint2*>(g_E_bf + (size_t)row * DIM);
    #pragma unroll
    for (int c = 0; c < 4; ++c) {
        __nv_bfloat162 p0 = __float22bfloat162_rn(make_float2(v[c].x, v[c].y));
        __nv_bfloat162 p1 = __float22bfloat162_rn(make_float2(v[c].z, v[c].w));
        uint2 u;
        u.x = *reinterpret_cast<uint32_t*>(&p0);
        u.y = *reinterpret_cast<uint32_t*>(&p1);
        dst[lane + 32 * c] = u;
    }
}

// ---------------- fused mma.sync GEMM + d2/min/label epilogue ----------------
// Grid (16, 128): x = 128-col tile, y = 128-row tile. 256 threads = 8 warps (2 M x 4 N).
// CTA tile 128x128, BK=64, 3-stage cp.async pipeline (ONE __syncthreads per k-iter),
// SW128 swizzle, occupancy 2. Warp tile 64x32 = 4x4 m16n8k16, fp32 accumulate.
#define STAGE_BYTES 32768         // A 16384 + B 16384
#define SMEM_B_IN_STAGE 16384
#define SMEM_RM_OFF (3 * STAGE_BYTES)          // 98304, 128 x 4B
#define SMEM_GEMM_TOTAL (SMEM_RM_OFF + 512)    // 98816

__global__ __launch_bounds__(256, 2)
void gemm_mma(const int* __restrict__ label) {
    extern __shared__ char smem[];
    const uint32_t smem_u32 = smem_to_u32(smem);
    const int tid  = threadIdx.x;
    const int lane = tid & 31;
    const int wid  = tid >> 5;
    const int warpM = wid >> 2;          // 0..1 -> rows warpM*64
    const int warpN = wid & 3;           // 0..3 -> cols warpN*32
    const int rowBase = blockIdx.y * 128;
    const int colBase = blockIdx.x * 128;

    unsigned* rowMinS = reinterpret_cast<unsigned*>(smem + SMEM_RM_OFF);
    if (tid < 128) rowMinS[tid] = 0x7F800000u;

    // stage loader: A 128x64 bf16 (1024 16B chunks) + B 128x64 (1024 chunks), 4+4/thread
    auto loadTile = [&](int kt, int s) {
        uint32_t sbase = smem_u32 + s * STAGE_BYTES;
        #pragma unroll
        for (int i = 0; i < 4; ++i) {
            int q = tid + 256 * i;           // 0..1023
            int row = q >> 3, kc = q & 7;
            const void* srcA = g_WO_bf + (size_t)(rowBase + row) * DIM + kt * 64 + kc * 8;
            CP_ASYNC_16(sbase + SW128(row * 128 + kc * 16), srcA);
            const void* srcB = g_E_bf + (size_t)(colBase + row) * DIM + kt * 64 + kc * 8;
            CP_ASYNC_16(sbase + SMEM_B_IN_STAGE + SW128(row * 128 + kc * 16), srcB);
        }
        CP_ASYNC_COMMIT();
    };

    float acc[4][4][4];
    #pragma unroll
    for (int mt = 0; mt < 4; ++mt)
        #pragma unroll
        for (int nt = 0; nt < 4; ++nt)
            #pragma unroll
            for (int e = 0; e < 4; ++e) acc[mt][nt][e] = 0.f;

    const int aRowOff = (warpM * 64 + (lane & 7) + ((lane >> 3) & 1) * 8) * 128 + (lane >> 4) * 16;
    const int bRowOff = (warpN * 32 + (lane & 7) + (lane >> 4) * 8) * 128 + ((lane >> 3) & 1) * 16;

    loadTile(0, 0);
    loadTile(1, 1);

    #pragma unroll 1
    for (int kt = 0; kt < 8; ++kt) {
        if (kt < 6) CP_ASYNC_WAIT1();   // stage kt resident (kt+1 may be in flight)
        else        CP_ASYNC_WAIT0();
        __syncthreads();                // also: all reads of stage kt-1 are done
        if (kt + 2 < 8) loadTile(kt + 2, (kt + 2) % 3);  // fills slot (kt-1)%3 — safe

        const uint32_t sA = smem_u32 + (kt % 3) * STAGE_BYTES;
        const uint32_t sB = sA + SMEM_B_IN_STAGE;
        #pragma unroll
        for (int ks = 0; ks < 4; ++ks) {
            uint32_t aF[4][4], bF[4][2];
            #pragma unroll
            for (int mt = 0; mt < 4; ++mt)
                ldsm_x4(aF[mt], sA + SW128(aRowOff + mt * 2048 + ks * 32));
            #pragma unroll
            for (int pr = 0; pr < 2; ++pr) {
                uint32_t t[4];
                ldsm_x4(t, sB + SW128(bRowOff + pr * 2048 + ks * 32));
                bF[2 * pr + 0][0] = t[0]; bF[2 * pr + 0][1] = t[1];
                bF[2 * pr + 1][0] = t[2]; bF[2 * pr + 1][1] = t[3];
            }
            #pragma unroll
            for (int mt = 0; mt < 4; ++mt)
                #pragma unroll
                for (int nt = 0; nt < 4; ++nt)
                    mma_16816(acc[mt][nt], aF[mt], bF[nt]);
        }
    }

    // epilogue in d^2 space: d2 = x2 + e2 - 2*dot; exclude label col from min
    #pragma unroll
    for (int mt = 0; mt < 4; ++mt) {
        #pragma unroll
        for (int half = 0; half < 2; ++half) {
            int rl = warpM * 64 + mt * 16 + (lane >> 2) + half * 8;
            int r  = rowBase + rl;
            float x2v = __ldg(&d_x2[r]);
            int   lab = __ldg(&label[r]);
            float m = __int_as_float(0x7f800000);
            #pragma unroll
            for (int nt = 0; nt < 4; ++nt) {
                int c0 = colBase + warpN * 32 + nt * 8 + 2 * (lane & 3);
                float d20 = fmaf(-2.f, acc[mt][nt][half * 2 + 0], x2v + __ldg(&d_e2[c0]));
                float d21 = fmaf(-2.f, acc[mt][nt][half * 2 + 1], x2v + __ldg(&d_e2[c0 + 1]));
                if (c0 == lab)     d_labelD2[r] = d20;
                else               m = fminf(m, d20);
                if (c0 + 1 == lab) d_labelD2[r] = d21;
                else               m = fminf(m, d21);
            }
            m = fminf(m, __shfl_xor_sync(0xffffffffu, m, 1));
            m = fminf(m, __shfl_xor_sync(0xffffffffu, m, 2));
            if ((lane & 3) == 0) atomicMin(&rowMinS[rl], __float_as_uint(m));
        }
    }
    __syncthreads();
    if (tid < 128)
        atomicMin(&d_minBits[rowBase + tid], rowMinS[tid]);
}

// ---------------- loss reduction (2-stage) ----------------
__global__ void partial_loss() {
    int tid = threadIdx.x;
    int n = blockIdx.x * 256 + tid;
    float ld = sqrtf(fmaxf(d_labelD2[n], 0.f));
    float md = sqrtf(fmaxf(__uint_as_float(d_minBits[n]), 0.f));
    float s = MARGIN + ld - md;
    #pragma unroll
    for (int off = 16; off > 0; off >>= 1) s += __shfl_xor_sync(0xffffffffu, s, off);
    __shared__ float sb[8];
    if ((tid & 31) == 0) sb[tid >> 5] = s;
    __syncthreads();
    if (tid < 8) {
        float v = sb[tid];
        v += __shfl_xor_sync(0xffu, v, 1);
        v += __shfl_xor_sync(0xffu, v, 2);
        v += __shfl_xor_sync(0xffu, v, 4);
        if (tid == 0) d_partial[blockIdx.x] = v;
    }
}
__global__ void final_loss(float* __restrict__ out) {
    int tid = threadIdx.x;   // 64
    float v = d_partial[tid];
    #pragma unroll
    for (int off = 16; off > 0; off >>= 1) v += __shfl_xor_sync(0xffffffffu, v, off);
    __shared__ float sb[2];
    if ((tid & 31) == 0) sb[tid >> 5] = v;
    __syncthreads();
    if (tid == 0) out[0] = (sb[0] + sb[1]) / (float)N_ROWS;
}

// ---------------- launch ----------------
extern "C" void kernel_launch(void* const* d_in, const int* in_sizes, int n_in,
                              void* d_out, int out_size) {
    const float* WO    = (const float*)d_in[0];
    const float* E     = (const float*)d_in[1];
    const int*   label = (const int*)d_in[2];
    float* out = (float*)d_out;

    cudaFuncSetAttribute(gemm_mma, cudaFuncAttributeMaxDynamicSharedMemorySize, SMEM_GEMM_TOTAL);

    prep_wo<<<N_ROWS / 8, 256>>>(WO);
    prep_e<<<N_CLS / 8, 256>>>(E);
    dim3 grid(N_CLS / 128, N_ROWS / 128);   // (16, 128)
    gemm_mma<<<grid, 256, SMEM_GEMM_TOTAL>>>(label);
    partial_loss<<<64, 256>>>();
    final_loss<<<1, 64>>>(out);
}